// round 6
// baseline (speedup 1.0000x reference)
#include <cuda_runtime.h>
#include <math.h>
#include <float.h>

#define NB 64
#define NG 32
#define NA 8400
#define NC 80
#define NCH 84
#define TOPK 13

// Scratch (device globals — no allocation allowed)
__device__ float         g_align[(size_t)NB * NG * NA];   // (B,G,A) layout, holds align^2
__device__ unsigned      g_inside[NB * NA];               // bit g: anchor inside gt g
__device__ unsigned char g_bestg[NB * NA];                // argmax_g iou (first max)
__device__ unsigned      g_cand[NB * NA];                 // bit g: topk(g) && inside
__device__ int           g_count;
__device__ int           g_ticket;

// ---------------------------------------------------------------------------
// Kernel 1: 4 anchors/thread, float4 everywhere. Stores align^2 (no sqrt),
// fast division, single-pass softmax denominator with __expf.
// ---------------------------------------------------------------------------
__global__ void __launch_bounds__(256) k1_align(const float* __restrict__ preds,
                                                const float* __restrict__ gtb,
                                                const int*   __restrict__ gtc,
                                                const float* __restrict__ anc)
{
    __shared__ float sx1[NG], sy1[NG], sx2[NG], sy2[NG], sar[NG];
    __shared__ int   scls[NG];
    const int b   = blockIdx.y;
    const int tid = threadIdx.x;
    if (tid < NG) {
        const float4 gp = *reinterpret_cast<const float4*>(gtb + ((size_t)b * NG + tid) * 4);
        sx1[tid] = gp.x; sy1[tid] = gp.y; sx2[tid] = gp.z; sy2[tid] = gp.w;
        sar[tid] = (gp.z - gp.x) * (gp.w - gp.y) + 1e-7f;   // area_g + IOU_EPS
        scls[tid] = gtc[b * NG + tid];
    }
    if (blockIdx.x == 0 && b == 0 && tid == 0) { g_count = 0; g_ticket = 0; }
    __syncthreads();

    const int a = (blockIdx.x * blockDim.x + tid) * 4;
    if (a >= NA) return;

    const float* pb = preds + (size_t)b * NCH * NA;

    float ax[4], ay[4];
    {
        const float4 a01 = *reinterpret_cast<const float4*>(anc + (size_t)a * 2);
        const float4 a23 = *reinterpret_cast<const float4*>(anc + (size_t)a * 2 + 4);
        ax[0] = a01.x; ay[0] = a01.y; ax[1] = a01.z; ay[1] = a01.w;
        ax[2] = a23.x; ay[2] = a23.y; ax[3] = a23.z; ay[3] = a23.w;
    }
    const float4 dl = *reinterpret_cast<const float4*>(pb + 0 * NA + a);
    const float4 dt = *reinterpret_cast<const float4*>(pb + 1 * NA + a);
    const float4 dr = *reinterpret_cast<const float4*>(pb + 2 * NA + a);
    const float4 db = *reinterpret_cast<const float4*>(pb + 3 * NA + a);
    const float dlv[4] = {dl.x, dl.y, dl.z, dl.w};
    const float dtv[4] = {dt.x, dt.y, dt.z, dt.w};
    const float drv[4] = {dr.x, dr.y, dr.z, dr.w};
    const float dbv[4] = {db.x, db.y, db.z, db.w};

    float px1[4], py1[4], px2[4], py2[4], areap[4];
    #pragma unroll
    for (int i = 0; i < 4; ++i) {
        px1[i] = ax[i] - dlv[i]; py1[i] = ay[i] - dtv[i];
        px2[i] = ax[i] + drv[i]; py2[i] = ay[i] + dbv[i];
        areap[i] = (px2[i] - px1[i]) * (py2[i] - py1[i]);
    }

    // single-pass softmax denominators
    float s0 = 0.f, s1 = 0.f, s2 = 0.f, s3 = 0.f;
    #pragma unroll 4
    for (int c = 0; c < NC; ++c) {
        const float4 x = *reinterpret_cast<const float4*>(pb + (size_t)(4 + c) * NA + a);
        s0 += __expf(x.x); s1 += __expf(x.y); s2 += __expf(x.z); s3 += __expf(x.w);
    }
    const float inv[4] = {__frcp_rn(s0), __frcp_rn(s1), __frcp_rn(s2), __frcp_rn(s3)};

    unsigned ins[4] = {0u, 0u, 0u, 0u};
    int   bg[4] = {0, 0, 0, 0};
    float bi[4] = {-1.f, -1.f, -1.f, -1.f};
    const size_t ba = (size_t)b * NA + a;

    #pragma unroll 2
    for (int g = 0; g < NG; ++g) {
        const float gx1 = sx1[g], gy1 = sy1[g], gx2 = sx2[g], gy2 = sy2[g];
        const float ag  = sar[g];
        const float4 lg4 = *reinterpret_cast<const float4*>(pb + (size_t)(4 + scls[g]) * NA + a);
        const float lgv[4] = {lg4.x, lg4.y, lg4.z, lg4.w};
        float al[4];
        #pragma unroll
        for (int i = 0; i < 4; ++i) {
            const float iw = fmaxf(fminf(px2[i], gx2) - fmaxf(px1[i], gx1), 0.f);
            const float ih = fmaxf(fminf(py2[i], gy2) - fmaxf(py1[i], gy1), 0.f);
            const float inter = iw * ih;
            const float iou = __fdividef(inter, areap[i] + ag - inter);
            if (iou > bi[i]) { bi[i] = iou; bg[i] = g; }   // first-max tie break
            const float dmin = fminf(fminf(ax[i] - gx1, ay[i] - gy1),
                                     fminf(gx2 - ax[i], gy2 - ay[i]));
            if (dmin > 1e-9f) ins[i] |= (1u << g);
            const float csc = __expf(lgv[i]) * inv[i];
            al[i] = fmaxf(iou, 1e-12f) * fmaxf(csc, 1e-12f);   // align^2 (monotone)
        }
        *reinterpret_cast<float4*>(&g_align[((size_t)b * NG + g) * NA + a]) =
            make_float4(al[0], al[1], al[2], al[3]);
    }
    *reinterpret_cast<uint4*>(&g_inside[ba]) = make_uint4(ins[0], ins[1], ins[2], ins[3]);
    *reinterpret_cast<uchar4*>(&g_bestg[ba]) =
        make_uchar4((unsigned char)bg[0], (unsigned char)bg[1],
                    (unsigned char)bg[2], (unsigned char)bg[3]);
    *reinterpret_cast<uint4*>(&g_cand[ba]) = make_uint4(0u, 0u, 0u, 0u);  // zero each replay
}

// ---------------------------------------------------------------------------
// Kernel 2: per-(b,g) top-13 over anchors on align^2.
// 128 threads: per-thread sorted top-13 (66 el/thread), warp-level pop-merge
// (no barriers), then warp 0 merges 4x13=52 keys. One __syncthreads total.
// Tie-break: lower index wins (key packs NA-idx; align^2 > 0 always).
// ---------------------------------------------------------------------------
__device__ __forceinline__ unsigned long long pack_key(float v, int ixv) {
    return ((unsigned long long)__float_as_uint(v) << 32) | (unsigned)(NA - ixv);
}

__global__ void __launch_bounds__(128) k2_topk()
{
    __shared__ unsigned long long skeys[4 * TOPK];
    const int g = blockIdx.x;
    const int b = blockIdx.y;
    const float* __restrict__ row = g_align + ((size_t)b * NG + g) * NA;

    float v[TOPK];
    int   ix[TOPK];
    #pragma unroll
    for (int k = 0; k < TOPK; ++k) { v[k] = -1.f; ix[k] = NA; }

    for (int i = threadIdx.x; i < NA; i += 128) {
        float cv = row[i];
        if (cv > v[TOPK - 1]) {
            int ci = i;
            #pragma unroll
            for (int k = 0; k < TOPK; ++k) {
                if (cv > v[k]) {
                    const float tv = v[k]; const int ti = ix[k];
                    v[k] = cv; ix[k] = ci; cv = tv; ci = ti;
                }
            }
        }
    }

    const int lane = threadIdx.x & 31;
    const int wid  = threadIdx.x >> 5;

    // warp-level 13-round pop-merge (all keys unique: index is in the key)
    unsigned long long head = pack_key(v[0], ix[0]);
    int pos = 0;
    #pragma unroll
    for (int it = 0; it < TOPK; ++it) {
        unsigned long long m = head;
        #pragma unroll
        for (int off = 16; off; off >>= 1) {
            const unsigned long long o = __shfl_xor_sync(0xffffffffu, m, off);
            if (o > m) m = o;
        }
        if (head == m) { ++pos; head = (pos < TOPK) ? pack_key(v[pos], ix[pos]) : 0ull; }
        if (lane == 0) skeys[wid * TOPK + it] = m;
    }
    __syncthreads();

    if (wid == 0) {
        const int n = 4 * TOPK;  // 52
        unsigned long long hi = (lane < n) ? skeys[lane] : 0ull;
        unsigned long long lo = (lane + 32 < n) ? skeys[lane + 32] : 0ull;
        if (lo > hi) { const unsigned long long t = hi; hi = lo; lo = t; }
        unsigned long long win = 0ull;
        #pragma unroll
        for (int it = 0; it < TOPK; ++it) {
            unsigned long long m = hi;
            #pragma unroll
            for (int off = 16; off; off >>= 1) {
                const unsigned long long o = __shfl_xor_sync(0xffffffffu, m, off);
                if (o > m) m = o;
            }
            if (hi == m) { hi = lo; lo = 0ull; }
            if (lane == it) win = m;
        }
        if (lane < TOPK) {
            const int ixw = NA - (int)(unsigned)(win & 0xffffffffu);
            const size_t bw = (size_t)b * NA + ixw;
            if ((g_inside[bw] >> g) & 1u) atomicOr(&g_cand[bw], 1u << g);
        }
    }
}

// ---------------------------------------------------------------------------
// Kernel 3: resolve assignment per anchor, write outputs; last block writes sum.
// out layout: tb(B,A,4) | tc(B,A) | ts(B,A) | fg(B,A) | fg_sum(1)  — all f32
// ---------------------------------------------------------------------------
__global__ void __launch_bounds__(256) k3_out(const float* __restrict__ gtb,
                                              const int*   __restrict__ gtc,
                                              float* __restrict__ out)
{
    __shared__ float sx1[NG], sy1[NG], sx2[NG], sy2[NG];
    __shared__ int   scls[NG];
    const int b   = blockIdx.y;
    const int tid = threadIdx.x;
    if (tid < NG) {
        const float4 gp = *reinterpret_cast<const float4*>(gtb + ((size_t)b * NG + tid) * 4);
        sx1[tid] = gp.x; sy1[tid] = gp.y; sx2[tid] = gp.z; sy2[tid] = gp.w;
        scls[tid] = gtc[b * NG + tid];
    }
    __syncthreads();

    const int a = blockIdx.x * blockDim.x + tid;
    bool fg = false;
    float x1 = 0.f, y1 = 0.f, x2 = 0.f, y2 = 0.f, ts = 0.f, tcf = 0.f;
    size_t ba = 0;

    if (a < NA) {
        ba = (size_t)b * NA + a;
        const unsigned m = g_cand[ba];
        const int pc = __popc(m);
        fg = (pc > 0);
        if (fg) {
            const int g = (pc > 1) ? (int)g_bestg[ba] : (__ffs(m) - 1);
            x1 = sx1[g]; y1 = sy1[g]; x2 = sx2[g]; y2 = sy2[g];
            tcf = (float)scls[g];
            ts  = sqrtf(g_align[((size_t)b * NG + g) * NA + a]);  // back from align^2
        }
    }

    const size_t BA = (size_t)NB * NA;
    if (a < NA) {
        *reinterpret_cast<float4*>(out + ba * 4) = make_float4(x1, y1, x2, y2);
        out[BA * 4 + ba] = tcf;
        out[BA * 5 + ba] = ts;
        out[BA * 6 + ba] = fg ? 1.f : 0.f;
    }
    const unsigned bal = __ballot_sync(0xffffffffu, fg);
    if ((tid & 31) == 0 && bal) atomicAdd(&g_count, __popc(bal));

    __syncthreads();
    if (tid == 0) {
        __threadfence();
        const int nblk = gridDim.x * gridDim.y;
        if (atomicAdd(&g_ticket, 1) == nblk - 1) {
            out[BA * 7] = (float)atomicAdd(&g_count, 0);
        }
    }
}

// ---------------------------------------------------------------------------
extern "C" void kernel_launch(void* const* d_in, const int* in_sizes, int n_in,
                              void* d_out, int out_size)
{
    const float* preds = (const float*)d_in[0];
    const float* gtb   = (const float*)d_in[1];
    const int*   gtc   = (const int*)  d_in[2];
    const float* anc   = (const float*)d_in[3];
    float*       out   = (float*)d_out;

    dim3 grid1((NA / 4 + 255) / 256, NB);   // 9 x 64
    k1_align<<<grid1, 256>>>(preds, gtb, gtc, anc);

    dim3 grid2(NG, NB);                     // 32 x 64
    k2_topk<<<grid2, 128>>>();

    dim3 grid3((NA + 255) / 256, NB);       // 33 x 64
    k3_out<<<grid3, 256>>>(gtb, gtc, out);
}

// round 7
// speedup vs baseline: 1.7942x; 1.7942x over previous
#include <cuda_runtime.h>
#include <math.h>
#include <float.h>

#define NB 64
#define NG 32
#define NA 8400
#define NC 80
#define NCH 84
#define TOPK 13

// Scratch (device globals — no allocation allowed)
__device__ float         g_align[(size_t)NB * NG * NA];   // (B,G,A) layout, holds align^2
__device__ unsigned      g_inside[NB * NA];               // bit g: anchor inside gt g
__device__ unsigned char g_bestg[NB * NA];                // argmax_g iou (first max)
__device__ unsigned      g_cand[NB * NA];                 // bit g: topk(g) && inside
__device__ int           g_count;
__device__ int           g_ticket;

// ---------------------------------------------------------------------------
// Kernel 1: 4 anchors/thread, float4 everywhere. Stores align^2 (no sqrt),
// fast division, single-pass softmax denominator with __expf.
// ---------------------------------------------------------------------------
__global__ void __launch_bounds__(256, 4) k1_align(const float* __restrict__ preds,
                                                   const float* __restrict__ gtb,
                                                   const int*   __restrict__ gtc,
                                                   const float* __restrict__ anc)
{
    __shared__ float sx1[NG], sy1[NG], sx2[NG], sy2[NG], sar[NG];
    __shared__ int   scls[NG];
    const int b   = blockIdx.y;
    const int tid = threadIdx.x;
    if (tid < NG) {
        const float4 gp = *reinterpret_cast<const float4*>(gtb + ((size_t)b * NG + tid) * 4);
        sx1[tid] = gp.x; sy1[tid] = gp.y; sx2[tid] = gp.z; sy2[tid] = gp.w;
        sar[tid] = (gp.z - gp.x) * (gp.w - gp.y) + 1e-7f;   // area_g + IOU_EPS
        scls[tid] = gtc[b * NG + tid];
    }
    if (blockIdx.x == 0 && b == 0 && tid == 0) { g_count = 0; g_ticket = 0; }
    __syncthreads();

    const int a = (blockIdx.x * blockDim.x + tid) * 4;
    if (a >= NA) return;

    const float* pb = preds + (size_t)b * NCH * NA;

    float ax[4], ay[4];
    {
        const float4 a01 = *reinterpret_cast<const float4*>(anc + (size_t)a * 2);
        const float4 a23 = *reinterpret_cast<const float4*>(anc + (size_t)a * 2 + 4);
        ax[0] = a01.x; ay[0] = a01.y; ax[1] = a01.z; ay[1] = a01.w;
        ax[2] = a23.x; ay[2] = a23.y; ax[3] = a23.z; ay[3] = a23.w;
    }
    const float4 dl = *reinterpret_cast<const float4*>(pb + 0 * NA + a);
    const float4 dt = *reinterpret_cast<const float4*>(pb + 1 * NA + a);
    const float4 dr = *reinterpret_cast<const float4*>(pb + 2 * NA + a);
    const float4 db = *reinterpret_cast<const float4*>(pb + 3 * NA + a);
    const float dlv[4] = {dl.x, dl.y, dl.z, dl.w};
    const float dtv[4] = {dt.x, dt.y, dt.z, dt.w};
    const float drv[4] = {dr.x, dr.y, dr.z, dr.w};
    const float dbv[4] = {db.x, db.y, db.z, db.w};

    float px1[4], py1[4], px2[4], py2[4], areap[4];
    #pragma unroll
    for (int i = 0; i < 4; ++i) {
        px1[i] = ax[i] - dlv[i]; py1[i] = ay[i] - dtv[i];
        px2[i] = ax[i] + drv[i]; py2[i] = ay[i] + dbv[i];
        areap[i] = (px2[i] - px1[i]) * (py2[i] - py1[i]);
    }

    // single-pass softmax denominators
    float s0 = 0.f, s1 = 0.f, s2 = 0.f, s3 = 0.f;
    #pragma unroll 4
    for (int c = 0; c < NC; ++c) {
        const float4 x = *reinterpret_cast<const float4*>(pb + (size_t)(4 + c) * NA + a);
        s0 += __expf(x.x); s1 += __expf(x.y); s2 += __expf(x.z); s3 += __expf(x.w);
    }
    const float inv[4] = {__frcp_rn(s0), __frcp_rn(s1), __frcp_rn(s2), __frcp_rn(s3)};

    unsigned ins[4] = {0u, 0u, 0u, 0u};
    int   bg[4] = {0, 0, 0, 0};
    float bi[4] = {-1.f, -1.f, -1.f, -1.f};
    const size_t ba = (size_t)b * NA + a;

    #pragma unroll 1
    for (int g = 0; g < NG; ++g) {
        const float gx1 = sx1[g], gy1 = sy1[g], gx2 = sx2[g], gy2 = sy2[g];
        const float ag  = sar[g];
        const float4 lg4 = *reinterpret_cast<const float4*>(pb + (size_t)(4 + scls[g]) * NA + a);
        const float lgv[4] = {lg4.x, lg4.y, lg4.z, lg4.w};
        float al[4];
        #pragma unroll
        for (int i = 0; i < 4; ++i) {
            const float iw = fmaxf(fminf(px2[i], gx2) - fmaxf(px1[i], gx1), 0.f);
            const float ih = fmaxf(fminf(py2[i], gy2) - fmaxf(py1[i], gy1), 0.f);
            const float inter = iw * ih;
            const float iou = __fdividef(inter, areap[i] + ag - inter);
            if (iou > bi[i]) { bi[i] = iou; bg[i] = g; }   // first-max tie break
            const float dmin = fminf(fminf(ax[i] - gx1, ay[i] - gy1),
                                     fminf(gx2 - ax[i], gy2 - ay[i]));
            if (dmin > 1e-9f) ins[i] |= (1u << g);
            const float csc = __expf(lgv[i]) * inv[i];
            al[i] = fmaxf(iou, 1e-12f) * fmaxf(csc, 1e-12f);   // align^2 (monotone)
        }
        *reinterpret_cast<float4*>(&g_align[((size_t)b * NG + g) * NA + a]) =
            make_float4(al[0], al[1], al[2], al[3]);
    }
    *reinterpret_cast<uint4*>(&g_inside[ba]) = make_uint4(ins[0], ins[1], ins[2], ins[3]);
    *reinterpret_cast<uchar4*>(&g_bestg[ba]) =
        make_uchar4((unsigned char)bg[0], (unsigned char)bg[1],
                    (unsigned char)bg[2], (unsigned char)bg[3]);
    *reinterpret_cast<uint4*>(&g_cand[ba]) = make_uint4(0u, 0u, 0u, 0u);  // zero each replay
}

// ---------------------------------------------------------------------------
// Kernel 2: per-(b,g) top-13 over align^2. 4 warps per row; each warp owns a
// 2100-element quarter and keeps a warp-DISTRIBUTED sorted top-13 (lanes 0..12
// hold u64 keys). Scan is float4 + ballot vs the shared 13th value; inserts
// are branchless shfl_up shifts and happen only ~66x per warp total.
// Key = (valbits<<32)|(NA-idx): value desc, tie -> lower index (jax top_k).
// ---------------------------------------------------------------------------
__device__ __forceinline__ unsigned long long pack_key(float v, int ixv) {
    return ((unsigned long long)__float_as_uint(v) << 32) | (unsigned)(NA - ixv);
}

__global__ void __launch_bounds__(128) k2_topk()
{
    __shared__ unsigned long long skeys[4 * TOPK];
    const int g = blockIdx.x;
    const int b = blockIdx.y;
    const float* __restrict__ row = g_align + ((size_t)b * NG + g) * NA;

    const int lane = threadIdx.x & 31;
    const int wid  = threadIdx.x >> 5;
    const int qbase = wid * (NA / 4);                 // 2100 floats per quarter
    const float4* __restrict__ qrow = reinterpret_cast<const float4*>(row + qbase);

    unsigned long long mykey = 0ull;                  // lanes 0..12: sorted desc
    unsigned long long kmin  = 0ull;
    float vminf = 0.0f;

    #pragma unroll 1
    for (int it = 0; it < 17; ++it) {                 // 525 float4 per quarter
        const int f4 = it * 32 + lane;
        float4 x = make_float4(-1.f, -1.f, -1.f, -1.f);
        if (f4 < 525) x = qrow[f4];
        const float xv[4] = {x.x, x.y, x.z, x.w};
        #pragma unroll
        for (int j = 0; j < 4; ++j) {
            unsigned bal = __ballot_sync(0xffffffffu, xv[j] >= vminf);
            while (bal) {
                const int src = __ffs(bal) - 1;       // warp-uniform
                bal &= bal - 1;
                const float bv = __shfl_sync(0xffffffffu, xv[j], src);
                const int bidx = qbase + (it * 32 + src) * 4 + j;
                const unsigned long long bkey = pack_key(bv, bidx);
                if (bkey > kmin) {                    // warp-uniform re-check
                    const unsigned long long up = __shfl_up_sync(0xffffffffu, mykey, 1);
                    if (lane < TOPK && bkey > mykey)
                        mykey = (lane == 0 || bkey <= up) ? bkey : up;
                    kmin  = __shfl_sync(0xffffffffu, mykey, TOPK - 1);
                    vminf = __uint_as_float((unsigned)(kmin >> 32));
                }
            }
        }
    }
    if (lane < TOPK) skeys[wid * TOPK + lane] = mykey;
    __syncthreads();

    if (wid == 0) {
        const int n = 4 * TOPK;  // 52 keys, all distinct, all > 0
        unsigned long long hi = (lane < n) ? skeys[lane] : 0ull;
        unsigned long long lo = (lane + 32 < n) ? skeys[lane + 32] : 0ull;
        if (lo > hi) { const unsigned long long t = hi; hi = lo; lo = t; }
        unsigned long long win = 0ull;
        #pragma unroll
        for (int it = 0; it < TOPK; ++it) {
            unsigned long long m = hi;
            #pragma unroll
            for (int off = 16; off; off >>= 1) {
                const unsigned long long o = __shfl_xor_sync(0xffffffffu, m, off);
                if (o > m) m = o;
            }
            if (hi == m) { hi = lo; lo = 0ull; }      // winner pops (keys unique)
            if (lane == it) win = m;
        }
        if (lane < TOPK) {
            const int ixw = NA - (int)(unsigned)(win & 0xffffffffu);
            const size_t bw = (size_t)b * NA + ixw;
            if ((g_inside[bw] >> g) & 1u) atomicOr(&g_cand[bw], 1u << g);
        }
    }
}

// ---------------------------------------------------------------------------
// Kernel 3: resolve assignment per anchor, write outputs; last block writes sum.
// out layout: tb(B,A,4) | tc(B,A) | ts(B,A) | fg(B,A) | fg_sum(1)  — all f32
// ---------------------------------------------------------------------------
__global__ void __launch_bounds__(256) k3_out(const float* __restrict__ gtb,
                                              const int*   __restrict__ gtc,
                                              float* __restrict__ out)
{
    __shared__ float sx1[NG], sy1[NG], sx2[NG], sy2[NG];
    __shared__ int   scls[NG];
    const int b   = blockIdx.y;
    const int tid = threadIdx.x;
    if (tid < NG) {
        const float4 gp = *reinterpret_cast<const float4*>(gtb + ((size_t)b * NG + tid) * 4);
        sx1[tid] = gp.x; sy1[tid] = gp.y; sx2[tid] = gp.z; sy2[tid] = gp.w;
        scls[tid] = gtc[b * NG + tid];
    }
    __syncthreads();

    const int a = blockIdx.x * blockDim.x + tid;
    bool fg = false;
    float x1 = 0.f, y1 = 0.f, x2 = 0.f, y2 = 0.f, ts = 0.f, tcf = 0.f;
    size_t ba = 0;

    if (a < NA) {
        ba = (size_t)b * NA + a;
        const unsigned m = g_cand[ba];
        const int pc = __popc(m);
        fg = (pc > 0);
        if (fg) {
            const int g = (pc > 1) ? (int)g_bestg[ba] : (__ffs(m) - 1);
            x1 = sx1[g]; y1 = sy1[g]; x2 = sx2[g]; y2 = sy2[g];
            tcf = (float)scls[g];
            ts  = sqrtf(g_align[((size_t)b * NG + g) * NA + a]);  // back from align^2
        }
    }

    const size_t BA = (size_t)NB * NA;
    if (a < NA) {
        *reinterpret_cast<float4*>(out + ba * 4) = make_float4(x1, y1, x2, y2);
        out[BA * 4 + ba] = tcf;
        out[BA * 5 + ba] = ts;
        out[BA * 6 + ba] = fg ? 1.f : 0.f;
    }
    const unsigned bal = __ballot_sync(0xffffffffu, fg);
    if ((tid & 31) == 0 && bal) atomicAdd(&g_count, __popc(bal));

    __syncthreads();
    if (tid == 0) {
        __threadfence();
        const int nblk = gridDim.x * gridDim.y;
        if (atomicAdd(&g_ticket, 1) == nblk - 1) {
            out[BA * 7] = (float)atomicAdd(&g_count, 0);
        }
    }
}

// ---------------------------------------------------------------------------
extern "C" void kernel_launch(void* const* d_in, const int* in_sizes, int n_in,
                              void* d_out, int out_size)
{
    const float* preds = (const float*)d_in[0];
    const float* gtb   = (const float*)d_in[1];
    const int*   gtc   = (const int*)  d_in[2];
    const float* anc   = (const float*)d_in[3];
    float*       out   = (float*)d_out;

    dim3 grid1((NA / 4 + 255) / 256, NB);   // 9 x 64
    k1_align<<<grid1, 256>>>(preds, gtb, gtc, anc);

    dim3 grid2(NG, NB);                     // 32 x 64
    k2_topk<<<grid2, 128>>>();

    dim3 grid3((NA + 255) / 256, NB);       // 33 x 64
    k3_out<<<grid3, 256>>>(gtb, gtc, out);
}